// round 5
// baseline (speedup 1.0000x reference)
#include <cuda_runtime.h>

// TT-embedding:
//   core0: (1,8,40,16)    A[x][p][b]     idx = x*640 + p*16 + b
//   core1: (16,8,32,16)   M[b][y][q][c]  idx = b*4096 + y*512 + q*16 + c
//   core2: (16,16,25,1)   C[c][z][r]     idx = c*400 + z*25 + r
//   id -> p = id/800, q = (id%800)/25, r = id%25
//   out[tok][x*128+y*16+z] = sum_{b,c} A[x][p][b] M[b][y][q][c] C[c][z][r]
//
// Stage 1: s[p*32+q][c][xy] = sum_b A[x][p][b] * M[b][y][q][c]   (5.2 MB, L2)
//          c2t[r][c][z]     = core2 transposed                    (25.6 KB)
// Stage 2: out[tok][xy][z] = sum_c s[pq][c][xy] * c2t[r][c][z]
//          TWO tokens per warp; 16 lanes/token; lane owns 4 xy rows;
//          z packed in f32x2 pairs; c2t broadcast from shared memory.

#define NTOK 16384
typedef unsigned long long ull;

__device__ float g_s[1280 * 1024];
__device__ __align__(16) float g_c2t[6400];
__device__ int g_ids64;

// ---------------------------------------------------------------------------
// Stage 1: build s table (+ c2t transpose + id-width sniff in block 0)
// ---------------------------------------------------------------------------
__global__ __launch_bounds__(256) void build_s(const float* __restrict__ c0,
                                               const float* __restrict__ c1,
                                               const float* __restrict__ c2,
                                               const int* __restrict__ ids) {
    int pq = blockIdx.x;
    int p = pq >> 5, q = pq & 31;

    __shared__ float sA[128];    // [x][b]
    __shared__ float sM[2048];   // [b][y][c]

    int t = threadIdx.x;
    if (t < 128) {
        int x = t >> 4, b = t & 15;
        sA[t] = c0[x * 640 + p * 16 + b];
    }
    for (int i = t; i < 2048; i += 256) {
        int b = i >> 7, y = (i >> 4) & 7, cc = i & 15;
        sM[i] = c1[b * 4096 + y * 512 + q * 16 + cc];
    }
    __syncthreads();

    for (int o = t; o < 1024; o += 256) {
        int cc = o >> 6, xy = o & 63;
        int x = xy >> 3, y = xy & 7;
        float acc = 0.f;
#pragma unroll
        for (int b = 0; b < 16; ++b)
            acc += sA[x * 16 + b] * sM[b * 128 + y * 16 + cc];
        g_s[pq * 1024 + o] = acc;
    }

    if (pq == 0) {
        for (int i = t; i < 6400; i += 256) {
            int r = i >> 8, cz = i & 255;
            int cc = cz >> 4, z = cz & 15;
            g_c2t[i] = c2[cc * 400 + z * 25 + r];
        }
        if (t == 0) {
            int ored = 0;
#pragma unroll
            for (int i = 0; i < 32; ++i) ored |= ids[2 * i + 1];
            g_ids64 = (ored == 0) ? 1 : 0;
        }
    }
}

// ---------------------------------------------------------------------------
// Stage 2: 2 tokens/warp, 16 lanes/token, lane owns xy rows 4j..4j+3.
// Per token per warp: 8 LDG.128 (s) + 32 LDS.128 (c2t) + 8 STG.128.
// ---------------------------------------------------------------------------
__global__ __launch_bounds__(256, 8) void tt_gather(const int* __restrict__ ids,
                                                    float* __restrict__ out) {
    __shared__ __align__(16) float Cs[6400];   // c2t copy [r][c][z]
    int t = threadIdx.x;
    {
        const float4* src = reinterpret_cast<const float4*>(g_c2t);
        float4* dst = reinterpret_cast<float4*>(Cs);
        for (int i = t; i < 1600; i += 256) dst[i] = src[i];
    }
    __syncthreads();

    int lane = t & 31, warp = t >> 5;
    int half = lane >> 4, j = lane & 15;
    int tok = (blockIdx.x * 8 + warp) * 2 + half;

    int id = g_ids64 ? __ldg(ids + 2 * tok) : __ldg(ids + tok);
    int p = id / 800;
    int rem = id - p * 800;
    int q = rem / 25;
    int r = rem - q * 25;

    // s[pq][c][4j..4j+3] = float4 at index c*16 + j
    const float4* srow =
        reinterpret_cast<const float4*>(g_s + (p * 32 + q) * 1024) + j;
    // c2t[r][c][z]: per c, 4 ulonglong2 at index c*4..c*4+3
    const ulonglong2* crow = reinterpret_cast<const ulonglong2*>(Cs + r * 256);

    ull acc[4][8];   // [row i][z-pair k]
#pragma unroll
    for (int i = 0; i < 4; ++i)
#pragma unroll
        for (int k = 0; k < 8; ++k) acc[i][k] = 0ull;

#pragma unroll
    for (int c = 0; c < 16; ++c) {
        float4 sv = __ldg(srow + c * 16);
        ull s0, s1, s2, s3;
        asm("mov.b64 %0,{%1,%1};" : "=l"(s0) : "f"(sv.x));
        asm("mov.b64 %0,{%1,%1};" : "=l"(s1) : "f"(sv.y));
        asm("mov.b64 %0,{%1,%1};" : "=l"(s2) : "f"(sv.z));
        asm("mov.b64 %0,{%1,%1};" : "=l"(s3) : "f"(sv.w));
#pragma unroll
        for (int k4 = 0; k4 < 4; ++k4) {
            ulonglong2 cv = crow[c * 4 + k4];   // z pairs 2*k4, 2*k4+1
            asm("fma.rn.f32x2 %0,%1,%2,%0;" : "+l"(acc[0][2*k4])   : "l"(s0), "l"(cv.x));
            asm("fma.rn.f32x2 %0,%1,%2,%0;" : "+l"(acc[0][2*k4+1]) : "l"(s0), "l"(cv.y));
            asm("fma.rn.f32x2 %0,%1,%2,%0;" : "+l"(acc[1][2*k4])   : "l"(s1), "l"(cv.x));
            asm("fma.rn.f32x2 %0,%1,%2,%0;" : "+l"(acc[1][2*k4+1]) : "l"(s1), "l"(cv.y));
            asm("fma.rn.f32x2 %0,%1,%2,%0;" : "+l"(acc[2][2*k4])   : "l"(s2), "l"(cv.x));
            asm("fma.rn.f32x2 %0,%1,%2,%0;" : "+l"(acc[2][2*k4+1]) : "l"(s2), "l"(cv.y));
            asm("fma.rn.f32x2 %0,%1,%2,%0;" : "+l"(acc[3][2*k4])   : "l"(s3), "l"(cv.x));
            asm("fma.rn.f32x2 %0,%1,%2,%0;" : "+l"(acc[3][2*k4+1]) : "l"(s3), "l"(cv.y));
        }
    }

    // lane writes rows 4j..4j+3 (16 floats each) of its token
    ulonglong2* o2 = reinterpret_cast<ulonglong2*>(
        out + (size_t)tok * 1024 + j * 64);
#pragma unroll
    for (int i = 0; i < 4; ++i)
#pragma unroll
        for (int k4 = 0; k4 < 4; ++k4)
            o2[i * 4 + k4] = make_ulonglong2(acc[i][2*k4], acc[i][2*k4+1]);
}

// ---------------------------------------------------------------------------
extern "C" void kernel_launch(void* const* d_in, const int* in_sizes, int n_in,
                              void* d_out, int out_size) {
    const float* core0 = (const float*)d_in[0];
    const float* core1 = (const float*)d_in[1];
    const float* core2 = (const float*)d_in[2];
    const int*   ids   = (const int*)d_in[3];
    float* out = (float*)d_out;

    build_s<<<1280, 256>>>(core0, core1, core2, ids);
    tt_gather<<<1024, 256>>>(ids, out);
}

// round 6
// speedup vs baseline: 4.5457x; 4.5457x over previous
#include <cuda_runtime.h>

// TT-embedding:
//   core0: (1,8,40,16)    A[x][p][b]     idx = x*640 + p*16 + b
//   core1: (16,8,32,16)   M[b][y][q][c]  idx = b*4096 + y*512 + q*16 + c
//   core2: (16,16,25,1)   C[c][z][r]     idx = c*400 + z*25 + r
//   id -> p = id/800, q = (id%800)/25, r = id%25
//   out[tok][x*128+y*16+z] = sum_{b,c} A[x][p][b] M[b][y][q][c] C[c][z][r]
//
// Stage 1: s[p*32+q][c][xy] = sum_b A[x][p][b] * M[b][y][q][c]   (5.2 MB, L2)
//          c2t[r][c][z]     = core2 transposed                    (25.6 KB)
// Stage 2: out[tok][xy][z] = sum_c s[pq][c][xy] * c2t[r][c][z]
//          TWO tokens per warp; 16 lanes/token; lane owns 4 xy rows;
//          z packed in f32x2 pairs; c2t broadcast from shared memory.
//          launch_bounds(256,2): <=128 regs, NO spill (R5's (256,8) spilled).

#define NTOK 16384
typedef unsigned long long ull;

__device__ float g_s[1280 * 1024];
__device__ __align__(16) float g_c2t[6400];
__device__ int g_ids64;

// ---------------------------------------------------------------------------
// Stage 1: build s table (+ c2t transpose + id-width sniff in block 0)
// ---------------------------------------------------------------------------
__global__ __launch_bounds__(256) void build_s(const float* __restrict__ c0,
                                               const float* __restrict__ c1,
                                               const float* __restrict__ c2,
                                               const int* __restrict__ ids) {
    int pq = blockIdx.x;
    int p = pq >> 5, q = pq & 31;

    __shared__ float sA[128];    // [x][b]
    __shared__ float sM[2048];   // [b][y][c]

    int t = threadIdx.x;
    if (t < 128) {
        int x = t >> 4, b = t & 15;
        sA[t] = c0[x * 640 + p * 16 + b];
    }
    for (int i = t; i < 2048; i += 256) {
        int b = i >> 7, y = (i >> 4) & 7, cc = i & 15;
        sM[i] = c1[b * 4096 + y * 512 + q * 16 + cc];
    }
    __syncthreads();

    for (int o = t; o < 1024; o += 256) {
        int cc = o >> 6, xy = o & 63;
        int x = xy >> 3, y = xy & 7;
        float acc = 0.f;
#pragma unroll
        for (int b = 0; b < 16; ++b)
            acc += sA[x * 16 + b] * sM[b * 128 + y * 16 + cc];
        g_s[pq * 1024 + o] = acc;
    }

    if (pq == 0) {
        for (int i = t; i < 6400; i += 256) {
            int r = i >> 8, cz = i & 255;
            int cc = cz >> 4, z = cz & 15;
            g_c2t[i] = c2[cc * 400 + z * 25 + r];
        }
        if (t == 0) {
            int ored = 0;
#pragma unroll
            for (int i = 0; i < 32; ++i) ored |= ids[2 * i + 1];
            g_ids64 = (ored == 0) ? 1 : 0;
        }
    }
}

// ---------------------------------------------------------------------------
// Stage 2: 2 tokens/warp, 16 lanes/token, lane owns xy rows 4j..4j+3.
// Per token per warp: 8 LDG.128 (s) + 32 LDS.128 (c2t) + 8 STG.128.
// ---------------------------------------------------------------------------
__global__ __launch_bounds__(256, 2) void tt_gather(const int* __restrict__ ids,
                                                    float* __restrict__ out) {
    __shared__ __align__(16) float Cs[6400];   // c2t copy [r][c][z]
    int t = threadIdx.x;
    {
        const float4* src = reinterpret_cast<const float4*>(g_c2t);
        float4* dst = reinterpret_cast<float4*>(Cs);
        for (int i = t; i < 1600; i += 256) dst[i] = src[i];
    }
    __syncthreads();

    int lane = t & 31, warp = t >> 5;
    int half = lane >> 4, j = lane & 15;
    int tok = (blockIdx.x * 8 + warp) * 2 + half;

    int id = g_ids64 ? __ldg(ids + 2 * tok) : __ldg(ids + tok);
    int p = id / 800;
    int rem = id - p * 800;
    int q = rem / 25;
    int r = rem - q * 25;

    // s[pq][c][4j..4j+3] = float4 at index c*16 + j
    const float4* srow =
        reinterpret_cast<const float4*>(g_s + (p * 32 + q) * 1024) + j;
    // c2t[r][c][z]: per c, 4 ulonglong2 at index c*4..c*4+3
    const ulonglong2* crow = reinterpret_cast<const ulonglong2*>(Cs + r * 256);

    ull acc[4][8];   // [row i][z-pair k]
#pragma unroll
    for (int i = 0; i < 4; ++i)
#pragma unroll
        for (int k = 0; k < 8; ++k) acc[i][k] = 0ull;

#pragma unroll
    for (int c = 0; c < 16; ++c) {
        float4 sv = __ldg(srow + c * 16);
        ull s0, s1, s2, s3;
        asm("mov.b64 %0,{%1,%1};" : "=l"(s0) : "f"(sv.x));
        asm("mov.b64 %0,{%1,%1};" : "=l"(s1) : "f"(sv.y));
        asm("mov.b64 %0,{%1,%1};" : "=l"(s2) : "f"(sv.z));
        asm("mov.b64 %0,{%1,%1};" : "=l"(s3) : "f"(sv.w));
#pragma unroll
        for (int k4 = 0; k4 < 4; ++k4) {
            ulonglong2 cv = crow[c * 4 + k4];   // z pairs 2*k4, 2*k4+1
            asm("fma.rn.f32x2 %0,%1,%2,%0;" : "+l"(acc[0][2*k4])   : "l"(s0), "l"(cv.x));
            asm("fma.rn.f32x2 %0,%1,%2,%0;" : "+l"(acc[0][2*k4+1]) : "l"(s0), "l"(cv.y));
            asm("fma.rn.f32x2 %0,%1,%2,%0;" : "+l"(acc[1][2*k4])   : "l"(s1), "l"(cv.x));
            asm("fma.rn.f32x2 %0,%1,%2,%0;" : "+l"(acc[1][2*k4+1]) : "l"(s1), "l"(cv.y));
            asm("fma.rn.f32x2 %0,%1,%2,%0;" : "+l"(acc[2][2*k4])   : "l"(s2), "l"(cv.x));
            asm("fma.rn.f32x2 %0,%1,%2,%0;" : "+l"(acc[2][2*k4+1]) : "l"(s2), "l"(cv.y));
            asm("fma.rn.f32x2 %0,%1,%2,%0;" : "+l"(acc[3][2*k4])   : "l"(s3), "l"(cv.x));
            asm("fma.rn.f32x2 %0,%1,%2,%0;" : "+l"(acc[3][2*k4+1]) : "l"(s3), "l"(cv.y));
        }
    }

    // lane writes rows 4j..4j+3 (16 floats each) of its token
    ulonglong2* o2 = reinterpret_cast<ulonglong2*>(
        out + (size_t)tok * 1024 + j * 64);
#pragma unroll
    for (int i = 0; i < 4; ++i)
#pragma unroll
        for (int k4 = 0; k4 < 4; ++k4)
            o2[i * 4 + k4] = make_ulonglong2(acc[i][2*k4], acc[i][2*k4+1]);
}

// ---------------------------------------------------------------------------
extern "C" void kernel_launch(void* const* d_in, const int* in_sizes, int n_in,
                              void* d_out, int out_size) {
    const float* core0 = (const float*)d_in[0];
    const float* core1 = (const float*)d_in[1];
    const float* core2 = (const float*)d_in[2];
    const int*   ids   = (const int*)d_in[3];
    float* out = (float*)d_out;

    build_s<<<1280, 256>>>(core0, core1, core2, ids);
    tt_gather<<<1024, 256>>>(ids, out);
}